// round 1
// baseline (speedup 1.0000x reference)
#include <cuda_runtime.h>

#define D 128
#define MAXN 100000
#define MAXE 1600000
#define BN_EPS 1e-5f

// ---- scratch (allocation-free: device globals) ----
__device__ float g_xw[(size_t)MAXN * D];    // x @ W
__device__ float g_acc[(size_t)MAXN * D];   // aggregated messages + bias
__device__ float g_deg[MAXN];
__device__ float g_dinv[MAXN];
__device__ float g_sum[D];
__device__ float g_sumsq[D];
__device__ float g_scale[D];
__device__ float g_shift[D];

// ---------- init: deg=1 (self-loop), zero BN accumulators ----------
__global__ void k_init(int n) {
    int i = blockIdx.x * blockDim.x + threadIdx.x;
    if (i < n) g_deg[i] = 1.0f;
    if (i < D) { g_sum[i] = 0.0f; g_sumsq[i] = 0.0f; }
}

// ---------- in-degree via atomics ----------
__global__ void k_deg(const int* __restrict__ dst, int E) {
    int e = blockIdx.x * blockDim.x + threadIdx.x;
    if (e < E) atomicAdd(&g_deg[dst[e]], 1.0f);
}

__global__ void k_dinv(int n) {
    int i = blockIdx.x * blockDim.x + threadIdx.x;
    if (i < n) g_dinv[i] = rsqrtf(g_deg[i]);
}

// ---------- GEMM: g_xw = X @ W  (fp32, 128x128 tile, 8x8 microtile) ----------
__global__ __launch_bounds__(256, 2)
void k_gemm(const float* __restrict__ X, const float* __restrict__ W, int n) {
    __shared__ float As[128][33];   // [row][k] padded
    __shared__ float Bs[32][128];   // [k][col]
    const int tid = threadIdx.x;          // 256 threads
    const int tx = tid & 15;               // col group: 16 * 8 = 128 cols
    const int ty = tid >> 4;               // row group: 16 * 8 = 128 rows
    const int row0 = blockIdx.x * 128;

    float acc[8][8];
#pragma unroll
    for (int i = 0; i < 8; i++)
#pragma unroll
        for (int j = 0; j < 8; j++) acc[i][j] = 0.0f;

    for (int k0 = 0; k0 < 128; k0 += 32) {
        // load A tile: 128 rows x 32 k
        {
            int m = tid >> 3;             // 0..31
            int kq = (tid & 7) * 4;       // 0,4,...,28
#pragma unroll
            for (int p = 0; p < 4; p++) {
                int r = p * 32 + m;
                int grow = row0 + r;
                float4 v = make_float4(0.f, 0.f, 0.f, 0.f);
                if (grow < n)
                    v = *(const float4*)&X[(size_t)grow * D + k0 + kq];
                As[r][kq + 0] = v.x; As[r][kq + 1] = v.y;
                As[r][kq + 2] = v.z; As[r][kq + 3] = v.w;
            }
        }
        // load B tile: 32 k x 128 cols
        {
            int kk = tid >> 5;            // 0..7
            int nq = (tid & 31) * 4;      // 0..124
#pragma unroll
            for (int p = 0; p < 4; p++) {
                int krow = p * 8 + kk;
                float4 v = *(const float4*)&W[(size_t)(k0 + krow) * D + nq];
                *(float4*)&Bs[krow][nq] = v;
            }
        }
        __syncthreads();

#pragma unroll
        for (int k = 0; k < 32; k++) {
            float a[8], bfr[8];
#pragma unroll
            for (int i = 0; i < 8; i++) a[i] = As[ty * 8 + i][k];
            float4 b0 = *(float4*)&Bs[k][tx * 8];
            float4 b1 = *(float4*)&Bs[k][tx * 8 + 4];
            bfr[0] = b0.x; bfr[1] = b0.y; bfr[2] = b0.z; bfr[3] = b0.w;
            bfr[4] = b1.x; bfr[5] = b1.y; bfr[6] = b1.z; bfr[7] = b1.w;
#pragma unroll
            for (int i = 0; i < 8; i++)
#pragma unroll
                for (int j = 0; j < 8; j++)
                    acc[i][j] = fmaf(a[i], bfr[j], acc[i][j]);
        }
        __syncthreads();
    }

#pragma unroll
    for (int i = 0; i < 8; i++) {
        int grow = row0 + ty * 8 + i;
        if (grow < n) {
            float4 v0 = make_float4(acc[i][0], acc[i][1], acc[i][2], acc[i][3]);
            float4 v1 = make_float4(acc[i][4], acc[i][5], acc[i][6], acc[i][7]);
            *(float4*)&g_xw[(size_t)grow * D + tx * 8]     = v0;
            *(float4*)&g_xw[(size_t)grow * D + tx * 8 + 4] = v1;
        }
    }
}

// ---------- acc = b + self-loop message (xw[i]*dinv[i]^2) ----------
__global__ void k_self(const float* __restrict__ b, int n) {
    int t = blockIdx.x * blockDim.x + threadIdx.x;
    if (t >= n * 32) return;
    int i = t >> 5, q = t & 31;
    float di = g_dinv[i];
    float c = di * di;
    float4 v = ((const float4*)g_xw)[(size_t)i * 32 + q];
    float4 bb = ((const float4*)b)[q];
    float4 r;
    r.x = fmaf(v.x, c, bb.x);
    r.y = fmaf(v.y, c, bb.y);
    r.z = fmaf(v.z, c, bb.z);
    r.w = fmaf(v.w, c, bb.w);
    ((float4*)g_acc)[(size_t)i * 32 + q] = r;
}

// ---------- edge scatter: one warp per edge ----------
__global__ void k_scatter(const int* __restrict__ src, const int* __restrict__ dst, int E) {
    int w = (blockIdx.x * blockDim.x + threadIdx.x) >> 5;
    int lane = threadIdx.x & 31;
    if (w >= E) return;
    int s = src[w], d = dst[w];
    float c = g_dinv[s] * g_dinv[d];
    float4 v = ((const float4*)g_xw)[(size_t)s * 32 + lane];
    float* p = &g_acc[(size_t)d * D + lane * 4];
    atomicAdd(p + 0, v.x * c);
    atomicAdd(p + 1, v.y * c);
    atomicAdd(p + 2, v.z * c);
    atomicAdd(p + 3, v.w * c);
}

// ---------- BN stats: per-column sum & sumsq ----------
__global__ void k_stats(int n) {
    int d = threadIdx.x;                   // 128 threads = one per column
    float s = 0.0f, s2 = 0.0f;
    for (int r = blockIdx.x; r < n; r += gridDim.x) {
        float v = g_acc[(size_t)r * D + d];
        s += v;
        s2 = fmaf(v, v, s2);
    }
    atomicAdd(&g_sum[d], s);
    atomicAdd(&g_sumsq[d], s2);
}

__global__ void k_bnparams(const float* __restrict__ gamma,
                           const float* __restrict__ beta, int n) {
    int d = threadIdx.x;
    float inv_n = 1.0f / (float)n;
    float mean = g_sum[d] * inv_n;
    float var = g_sumsq[d] * inv_n - mean * mean;
    float sc = gamma[d] * rsqrtf(var + BN_EPS);
    g_scale[d] = sc;
    g_shift[d] = fmaf(-mean, sc, beta[d]);
}

// ---------- finalize: BN affine + PReLU + residual ----------
__global__ void k_final(const float* __restrict__ x,
                        const float* __restrict__ a_prelu,
                        float* __restrict__ out, int n) {
    int t = blockIdx.x * blockDim.x + threadIdx.x;
    if (t >= n * 32) return;
    int q = t & 31;
    float a = *a_prelu;
    float4 v  = ((const float4*)g_acc)[t];
    float4 sc = ((const float4*)g_scale)[q];
    float4 sh = ((const float4*)g_shift)[q];
    float4 xx = ((const float4*)x)[t];
    float4 r;
    r.x = fmaf(v.x, sc.x, sh.x); r.x = (r.x > 0.f ? r.x : a * r.x) + xx.x;
    r.y = fmaf(v.y, sc.y, sh.y); r.y = (r.y > 0.f ? r.y : a * r.y) + xx.y;
    r.z = fmaf(v.z, sc.z, sh.z); r.z = (r.z > 0.f ? r.z : a * r.z) + xx.z;
    r.w = fmaf(v.w, sc.w, sh.w); r.w = (r.w > 0.f ? r.w : a * r.w) + xx.w;
    ((float4*)out)[t] = r;
}

extern "C" void kernel_launch(void* const* d_in, const int* in_sizes, int n_in,
                              void* d_out, int out_size) {
    const float* x       = (const float*)d_in[0];
    const float* W       = (const float*)d_in[1];
    const float* b       = (const float*)d_in[2];
    const float* gamma   = (const float*)d_in[3];
    const float* beta    = (const float*)d_in[4];
    const float* a_prelu = (const float*)d_in[5];
    const int*   ei      = (const int*)d_in[6];

    int n = in_sizes[0] / D;
    int E = in_sizes[6] / 2;
    const int* src = ei;
    const int* dst = ei + E;
    float* out = (float*)d_out;

    k_init<<<(n + 255) / 256, 256>>>(n);
    k_deg<<<(E + 255) / 256, 256>>>(dst, E);
    k_dinv<<<(n + 255) / 256, 256>>>(n);
    k_gemm<<<(n + 127) / 128, 256>>>(x, W, n);
    k_self<<<(n * 32 + 255) / 256, 256>>>(b, n);
    {
        long long threads = (long long)E * 32;
        int blocks = (int)((threads + 255) / 256);
        k_scatter<<<blocks, 256>>>(src, dst, E);
    }
    k_stats<<<240, 128>>>(n);
    k_bnparams<<<1, 128>>>(gamma, beta, n);
    k_final<<<(n * 32 + 255) / 256, 256>>>(x, a_prelu, out, n);
}

// round 2
// speedup vs baseline: 3.0484x; 3.0484x over previous
#include <cuda_runtime.h>

#define D 128
#define MAXN 100000
#define MAXE 1600000
#define BN_EPS 1e-5f

#define SCAN_TPB 256
#define SCAN_EPT 8
#define SCAN_EPB (SCAN_TPB * SCAN_EPT)          // 2048
#define SCAN_BLOCKS ((MAXN + SCAN_EPB - 1) / SCAN_EPB)  // 49

// ---- scratch (allocation-free: device globals) ----
__device__ float g_xw[(size_t)MAXN * D];    // x @ W
__device__ float g_acc[(size_t)MAXN * D];   // aggregated messages + bias
__device__ int   g_degi[MAXN];              // in-degree (excl. self-loop)
__device__ float g_dinv[MAXN];
__device__ int   g_rowstart[MAXN];          // exclusive scan of degi
__device__ int   g_cursor[MAXN];            // fill cursors
__device__ int   g_csr_src[MAXE];           // src ids binned by dst
__device__ int   g_blocksum[SCAN_BLOCKS + 8];
__device__ float g_sum[D];
__device__ float g_sumsq[D];
__device__ float g_scale[D];
__device__ float g_shift[D];

// ---------- init: zero degree + BN accumulators ----------
__global__ void k_init(int n) {
    int i = blockIdx.x * blockDim.x + threadIdx.x;
    if (i < n) g_degi[i] = 0;
    if (i < D) { g_sum[i] = 0.0f; g_sumsq[i] = 0.0f; }
}

// ---------- in-degree via int atomics ----------
__global__ void k_deg(const int* __restrict__ dst, int E) {
    int e = blockIdx.x * blockDim.x + threadIdx.x;
    if (e < E) atomicAdd(&g_degi[dst[e]], 1);
}

// ---------- exclusive scan of g_degi -> g_rowstart (3 kernels) ----------
__global__ void k_scan1(int n) {
    __shared__ int warpsum[8];
    const int b = blockIdx.x;
    const int t = threadIdx.x;
    const int base = b * SCAN_EPB + t * SCAN_EPT;
    int v[SCAN_EPT];
    int local = 0;
#pragma unroll
    for (int j = 0; j < SCAN_EPT; j++) {
        int idx = base + j;
        v[j] = (idx < n) ? g_degi[idx] : 0;
        local += v[j];
    }
    int lane = t & 31, w = t >> 5;
    int x = local;
#pragma unroll
    for (int off = 1; off < 32; off <<= 1) {
        int y = __shfl_up_sync(0xffffffff, x, off);
        if (lane >= off) x += y;
    }
    if (lane == 31) warpsum[w] = x;
    __syncthreads();
    if (w == 0) {
        int s = (lane < 8) ? warpsum[lane] : 0;
#pragma unroll
        for (int off = 1; off < 8; off <<= 1) {
            int y = __shfl_up_sync(0xffffffff, s, off);
            if (lane >= off) s += y;
        }
        if (lane < 8) warpsum[lane] = s;
    }
    __syncthreads();
    int excl = x - local + ((w > 0) ? warpsum[w - 1] : 0);
    int run = excl;
#pragma unroll
    for (int j = 0; j < SCAN_EPT; j++) {
        int idx = base + j;
        if (idx < n) g_rowstart[idx] = run;
        run += v[j];
    }
    if (t == 0) g_blocksum[b] = warpsum[7];
}

__global__ void k_scan2(int nblocks) {
    if (threadIdx.x == 0) {
        int s = 0;
        for (int b = 0; b < nblocks; b++) {
            int t = g_blocksum[b];
            g_blocksum[b] = s;
            s += t;
        }
    }
}

__global__ void k_scan3(int n) {
    int i = blockIdx.x * blockDim.x + threadIdx.x;
    if (i >= n) return;
    int rs = g_rowstart[i] + g_blocksum[i / SCAN_EPB];
    g_rowstart[i] = rs;
    g_cursor[i] = rs;
    g_dinv[i] = rsqrtf(1.0f + (float)g_degi[i]);
}

// ---------- fill CSR: bin src ids by dst ----------
__global__ void k_fill(const int* __restrict__ src, const int* __restrict__ dst, int E) {
    int e = blockIdx.x * blockDim.x + threadIdx.x;
    if (e >= E) return;
    int d = dst[e];
    int pos = atomicAdd(&g_cursor[d], 1);
    g_csr_src[pos] = src[e];
}

// ---------- GEMM: g_xw = X @ W  (fp32, 128x128 tile, 8x8 microtile) ----------
__global__ __launch_bounds__(256, 2)
void k_gemm(const float* __restrict__ X, const float* __restrict__ W, int n) {
    __shared__ float As[128][33];
    __shared__ float Bs[32][128];
    const int tid = threadIdx.x;
    const int tx = tid & 15;
    const int ty = tid >> 4;
    const int row0 = blockIdx.x * 128;

    float acc[8][8];
#pragma unroll
    for (int i = 0; i < 8; i++)
#pragma unroll
        for (int j = 0; j < 8; j++) acc[i][j] = 0.0f;

    for (int k0 = 0; k0 < 128; k0 += 32) {
        {
            int m = tid >> 3;
            int kq = (tid & 7) * 4;
#pragma unroll
            for (int p = 0; p < 4; p++) {
                int r = p * 32 + m;
                int grow = row0 + r;
                float4 v = make_float4(0.f, 0.f, 0.f, 0.f);
                if (grow < n)
                    v = *(const float4*)&X[(size_t)grow * D + k0 + kq];
                As[r][kq + 0] = v.x; As[r][kq + 1] = v.y;
                As[r][kq + 2] = v.z; As[r][kq + 3] = v.w;
            }
        }
        {
            int kk = tid >> 5;
            int nq = (tid & 31) * 4;
#pragma unroll
            for (int p = 0; p < 4; p++) {
                int krow = p * 8 + kk;
                float4 v = *(const float4*)&W[(size_t)(k0 + krow) * D + nq];
                *(float4*)&Bs[krow][nq] = v;
            }
        }
        __syncthreads();

#pragma unroll
        for (int k = 0; k < 32; k++) {
            float a[8], bfr[8];
#pragma unroll
            for (int i = 0; i < 8; i++) a[i] = As[ty * 8 + i][k];
            float4 b0 = *(float4*)&Bs[k][tx * 8];
            float4 b1 = *(float4*)&Bs[k][tx * 8 + 4];
            bfr[0] = b0.x; bfr[1] = b0.y; bfr[2] = b0.z; bfr[3] = b0.w;
            bfr[4] = b1.x; bfr[5] = b1.y; bfr[6] = b1.z; bfr[7] = b1.w;
#pragma unroll
            for (int i = 0; i < 8; i++)
#pragma unroll
                for (int j = 0; j < 8; j++)
                    acc[i][j] = fmaf(a[i], bfr[j], acc[i][j]);
        }
        __syncthreads();
    }

#pragma unroll
    for (int i = 0; i < 8; i++) {
        int grow = row0 + ty * 8 + i;
        if (grow < n) {
            float4 v0 = make_float4(acc[i][0], acc[i][1], acc[i][2], acc[i][3]);
            float4 v1 = make_float4(acc[i][4], acc[i][5], acc[i][6], acc[i][7]);
            *(float4*)&g_xw[(size_t)grow * D + tx * 8]     = v0;
            *(float4*)&g_xw[(size_t)grow * D + tx * 8 + 4] = v1;
        }
    }
}

// ---------- pull aggregation: one warp per dst row, no feature atomics ----
// acc = b + xw[row]*dinv[row]^2 + sum_e xw[src_e]*dinv[src_e]*dinv[row]
// BN stats accumulated in registers, reduced via smem, one atomic/col/block.
__global__ __launch_bounds__(256)
void k_aggregate(const float* __restrict__ b, int n) {
    __shared__ float bs1[D];
    __shared__ float bs2[D];
    const int lane = threadIdx.x & 31;
    const int warp = threadIdx.x >> 5;
    const int warpGlobal = blockIdx.x * 8 + warp;
    const int totalWarps = gridDim.x * 8;

    if (threadIdx.x < D) { bs1[threadIdx.x] = 0.0f; bs2[threadIdx.x] = 0.0f; }
    __syncthreads();

    float4 bb = ((const float4*)b)[lane];
    float s1x = 0.f, s1y = 0.f, s1z = 0.f, s1w = 0.f;
    float s2x = 0.f, s2y = 0.f, s2z = 0.f, s2w = 0.f;

    for (int row = warpGlobal; row < n; row += totalWarps) {
        float dd = g_dinv[row];
        float selfc = dd * dd;
        float4 acc = bb;
        float4 xv = ((const float4*)g_xw)[(size_t)row * 32 + lane];
        acc.x = fmaf(xv.x, selfc, acc.x);
        acc.y = fmaf(xv.y, selfc, acc.y);
        acc.z = fmaf(xv.z, selfc, acc.z);
        acc.w = fmaf(xv.w, selfc, acc.w);

        int rs = g_rowstart[row];
        int deg = g_degi[row];
        for (int base = 0; base < deg; base += 32) {
            int e = base + lane;
            int s = 0; float cl = 0.0f;
            if (e < deg) {
                s = g_csr_src[rs + e];
                cl = g_dinv[s];
            }
            int cnt = min(32, deg - base);
            for (int j = 0; j < cnt; j++) {
                int sj = __shfl_sync(0xffffffff, s, j);
                float cj = __shfl_sync(0xffffffff, cl, j) * dd;
                float4 v = ((const float4*)g_xw)[(size_t)sj * 32 + lane];
                acc.x = fmaf(v.x, cj, acc.x);
                acc.y = fmaf(v.y, cj, acc.y);
                acc.z = fmaf(v.z, cj, acc.z);
                acc.w = fmaf(v.w, cj, acc.w);
            }
        }
        ((float4*)g_acc)[(size_t)row * 32 + lane] = acc;

        s1x += acc.x; s1y += acc.y; s1z += acc.z; s1w += acc.w;
        s2x = fmaf(acc.x, acc.x, s2x);
        s2y = fmaf(acc.y, acc.y, s2y);
        s2z = fmaf(acc.z, acc.z, s2z);
        s2w = fmaf(acc.w, acc.w, s2w);
    }

    atomicAdd(&bs1[lane * 4 + 0], s1x);
    atomicAdd(&bs1[lane * 4 + 1], s1y);
    atomicAdd(&bs1[lane * 4 + 2], s1z);
    atomicAdd(&bs1[lane * 4 + 3], s1w);
    atomicAdd(&bs2[lane * 4 + 0], s2x);
    atomicAdd(&bs2[lane * 4 + 1], s2y);
    atomicAdd(&bs2[lane * 4 + 2], s2z);
    atomicAdd(&bs2[lane * 4 + 3], s2w);
    __syncthreads();
    if (threadIdx.x < D) {
        atomicAdd(&g_sum[threadIdx.x], bs1[threadIdx.x]);
        atomicAdd(&g_sumsq[threadIdx.x], bs2[threadIdx.x]);
    }
}

__global__ void k_bnparams(const float* __restrict__ gamma,
                           const float* __restrict__ beta, int n) {
    int d = threadIdx.x;
    float inv_n = 1.0f / (float)n;
    float mean = g_sum[d] * inv_n;
    float var = g_sumsq[d] * inv_n - mean * mean;
    float sc = gamma[d] * rsqrtf(var + BN_EPS);
    g_scale[d] = sc;
    g_shift[d] = fmaf(-mean, sc, beta[d]);
}

// ---------- finalize: BN affine + PReLU + residual ----------
__global__ void k_final(const float* __restrict__ x,
                        const float* __restrict__ a_prelu,
                        float* __restrict__ out, int n) {
    int t = blockIdx.x * blockDim.x + threadIdx.x;
    if (t >= n * 32) return;
    int q = t & 31;
    float a = *a_prelu;
    float4 v  = ((const float4*)g_acc)[t];
    float4 sc = ((const float4*)g_scale)[q];
    float4 sh = ((const float4*)g_shift)[q];
    float4 xx = ((const float4*)x)[t];
    float4 r;
    r.x = fmaf(v.x, sc.x, sh.x); r.x = (r.x > 0.f ? r.x : a * r.x) + xx.x;
    r.y = fmaf(v.y, sc.y, sh.y); r.y = (r.y > 0.f ? r.y : a * r.y) + xx.y;
    r.z = fmaf(v.z, sc.z, sh.z); r.z = (r.z > 0.f ? r.z : a * r.z) + xx.z;
    r.w = fmaf(v.w, sc.w, sh.w); r.w = (r.w > 0.f ? r.w : a * r.w) + xx.w;
    ((float4*)out)[t] = r;
}

extern "C" void kernel_launch(void* const* d_in, const int* in_sizes, int n_in,
                              void* d_out, int out_size) {
    const float* x       = (const float*)d_in[0];
    const float* W       = (const float*)d_in[1];
    const float* b       = (const float*)d_in[2];
    const float* gamma   = (const float*)d_in[3];
    const float* beta    = (const float*)d_in[4];
    const float* a_prelu = (const float*)d_in[5];
    const int*   ei      = (const int*)d_in[6];

    int n = in_sizes[0] / D;
    int E = in_sizes[6] / 2;
    const int* src = ei;
    const int* dst = ei + E;
    float* out = (float*)d_out;

    int scanBlocks = (n + SCAN_EPB - 1) / SCAN_EPB;

    k_init<<<(n + 255) / 256, 256>>>(n);
    k_deg<<<(E + 255) / 256, 256>>>(dst, E);
    k_scan1<<<scanBlocks, SCAN_TPB>>>(n);
    k_scan2<<<1, 32>>>(scanBlocks);
    k_scan3<<<(n + 255) / 256, 256>>>(n);
    k_fill<<<(E + 255) / 256, 256>>>(src, dst, E);
    k_gemm<<<(n + 127) / 128, 256>>>(x, W, n);
    k_aggregate<<<2048, 256>>>(b, n);
    k_bnparams<<<1, 128>>>(gamma, beta, n);
    k_final<<<(n * 32 + 255) / 256, 256>>>(x, a_prelu, out, n);
}

// round 4
// speedup vs baseline: 3.1537x; 1.0346x over previous
#include <cuda_runtime.h>

#define D 128
#define MAXN 100000
#define MAXE 1600000
#define BN_EPS 1e-5f

#define SCAN_TPB 256
#define SCAN_EPT 8
#define SCAN_EPB (SCAN_TPB * SCAN_EPT)          // 2048
#define SCAN_BLOCKS ((MAXN + SCAN_EPB - 1) / SCAN_EPB)  // 49

typedef unsigned long long ull;

__device__ __forceinline__ ull ffma2(ull a, ull b, ull c) {
    ull d;
    asm("fma.rn.f32x2 %0, %1, %2, %3;" : "=l"(d) : "l"(a), "l"(b), "l"(c));
    return d;
}
__device__ __forceinline__ ull dup2(float x) {
    ull d;
    asm("mov.b64 %0, {%1, %1};" : "=l"(d) : "f"(x));
    return d;
}

// ---- scratch (allocation-free: device globals) ----
__device__ float g_xw[(size_t)MAXN * D];    // x @ W
__device__ float g_acc[(size_t)MAXN * D];   // aggregated messages + bias
__device__ int   g_degi[MAXN];              // in-degree (excl. self-loop)
__device__ float g_dinv[MAXN];
__device__ int   g_rowstart[MAXN];          // exclusive scan of degi
__device__ int   g_cursor[MAXN];            // fill cursors
__device__ int   g_csr_src[MAXE];           // src ids binned by dst
__device__ int   g_blocksum[SCAN_BLOCKS + 8];
__device__ float g_sum[D];
__device__ float g_sumsq[D];
__device__ float g_scale[D];
__device__ float g_shift[D];

// ---------- init: zero degree + BN accumulators ----------
__global__ void k_init(int n) {
    int i = blockIdx.x * blockDim.x + threadIdx.x;
    if (i < n) g_degi[i] = 0;
    if (i < D) { g_sum[i] = 0.0f; g_sumsq[i] = 0.0f; }
}

// ---------- in-degree via int atomics ----------
__global__ void k_deg(const int* __restrict__ dst, int E) {
    int e = blockIdx.x * blockDim.x + threadIdx.x;
    if (e < E) atomicAdd(&g_degi[dst[e]], 1);
}

// ---------- exclusive scan of g_degi -> g_rowstart (3 kernels) ----------
__global__ void k_scan1(int n) {
    __shared__ int warpsum[8];
    const int b = blockIdx.x;
    const int t = threadIdx.x;
    const int base = b * SCAN_EPB + t * SCAN_EPT;
    int v[SCAN_EPT];
    int local = 0;
#pragma unroll
    for (int j = 0; j < SCAN_EPT; j++) {
        int idx = base + j;
        v[j] = (idx < n) ? g_degi[idx] : 0;
        local += v[j];
    }
    int lane = t & 31, w = t >> 5;
    int x = local;
#pragma unroll
    for (int off = 1; off < 32; off <<= 1) {
        int y = __shfl_up_sync(0xffffffff, x, off);
        if (lane >= off) x += y;
    }
    if (lane == 31) warpsum[w] = x;
    __syncthreads();
    if (w == 0) {
        int s = (lane < 8) ? warpsum[lane] : 0;
#pragma unroll
        for (int off = 1; off < 8; off <<= 1) {
            int y = __shfl_up_sync(0xffffffff, s, off);
            if (lane >= off) s += y;
        }
        if (lane < 8) warpsum[lane] = s;
    }
    __syncthreads();
    int excl = x - local + ((w > 0) ? warpsum[w - 1] : 0);
    int run = excl;
#pragma unroll
    for (int j = 0; j < SCAN_EPT; j++) {
        int idx = base + j;
        if (idx < n) g_rowstart[idx] = run;
        run += v[j];
    }
    if (t == 0) g_blocksum[b] = warpsum[7];
}

// parallel exclusive scan of block sums (nblocks <= 256)
__global__ void k_scan2(int nblocks) {
    __shared__ int sh[256];
    int t = threadIdx.x;
    int v = (t < nblocks) ? g_blocksum[t] : 0;
    sh[t] = v;
    __syncthreads();
#pragma unroll
    for (int off = 1; off < 256; off <<= 1) {
        int y = (t >= off) ? sh[t - off] : 0;
        __syncthreads();
        sh[t] += y;
        __syncthreads();
    }
    if (t < nblocks) g_blocksum[t] = sh[t] - v;
}

__global__ void k_scan3(int n) {
    int i = blockIdx.x * blockDim.x + threadIdx.x;
    if (i >= n) return;
    int rs = g_rowstart[i] + g_blocksum[i / SCAN_EPB];
    g_rowstart[i] = rs;
    g_cursor[i] = rs;
    g_dinv[i] = rsqrtf(1.0f + (float)g_degi[i]);
}

// ---------- fill CSR: bin src ids by dst ----------
__global__ void k_fill(const int* __restrict__ src, const int* __restrict__ dst, int E) {
    int e = blockIdx.x * blockDim.x + threadIdx.x;
    if (e >= E) return;
    int d = dst[e];
    int pos = atomicAdd(&g_cursor[d], 1);
    g_csr_src[pos] = src[e];
}

// ---------- GEMM: g_xw = X @ W  (packed f32x2 FFMA2, 128x128 tile) ----------
// Thread (tx,ty): rows ty*8..ty*8+7, cols {tx*4..tx*4+3} and {64+tx*4..64+tx*4+3}
__global__ __launch_bounds__(256)
void k_gemm(const float* __restrict__ X, const float* __restrict__ W, int n) {
    __shared__ float Ast[32][132];   // [k][row] transposed; 132*4=528B stride (16B aligned)
    __shared__ float Bs[32][128];    // [k][col]
    const int tid = threadIdx.x;
    const int tx = tid & 15;
    const int ty = tid >> 4;
    const int row0 = blockIdx.x * 128;

    // acc2[i][p]: p=0 -> cols (tx*4, tx*4+1); p=1 -> (tx*4+2, +3);
    //             p=2 -> (64+tx*4, +1);     p=3 -> (64+tx*4+2, +3)
    ull acc2[8][4];
#pragma unroll
    for (int i = 0; i < 8; i++)
#pragma unroll
        for (int p = 0; p < 4; p++) acc2[i][p] = 0ull;

    const int m = tid >> 3;             // 0..31 (A load row-in-group)
    const int kq = (tid & 7) * 4;       // A load k-quad
    const int kk = tid >> 5;            // B load k-row group
    const int nq = (tid & 31) * 4;      // B load col quad

    for (int k0 = 0; k0 < 128; k0 += 32) {
        // load A tile (128 rows x 32 k), store TRANSPOSED: Ast[k][row]
#pragma unroll
        for (int p = 0; p < 4; p++) {
            int r = p * 32 + m;
            int grow = row0 + r;
            float4 v = make_float4(0.f, 0.f, 0.f, 0.f);
            if (grow < n)
                v = *(const float4*)&X[(size_t)grow * D + k0 + kq];
            Ast[kq + 0][r] = v.x;
            Ast[kq + 1][r] = v.y;
            Ast[kq + 2][r] = v.z;
            Ast[kq + 3][r] = v.w;
        }
        // load B tile (32 k x 128 cols)
#pragma unroll
        for (int p = 0; p < 4; p++) {
            int krow = p * 8 + kk;
            float4 v = *(const float4*)&W[(size_t)(k0 + krow) * D + nq];
            *(float4*)&Bs[krow][nq] = v;
        }
        __syncthreads();

#pragma unroll
        for (int k = 0; k < 32; k++) {
            float4 a0 = *(const float4*)&Ast[k][ty * 8];
            float4 a1 = *(const float4*)&Ast[k][ty * 8 + 4];
            ull ad[8];
            ad[0] = dup2(a0.x); ad[1] = dup2(a0.y);
            ad[2] = dup2(a0.z); ad[3] = dup2(a0.w);
            ad[4] = dup2(a1.x); ad[5] = dup2(a1.y);
            ad[6] = dup2(a1.z); ad[7] = dup2(a1.w);
            ull b0 = *(const ull*)&Bs[k][tx * 4];
            ull b1 = *(const ull*)&Bs[k][tx * 4 + 2];
            ull b2 = *(const ull*)&Bs[k][64 + tx * 4];
            ull b3 = *(const ull*)&Bs[k][64 + tx * 4 + 2];
#pragma unroll
            for (int i = 0; i < 8; i++) {
                acc2[i][0] = ffma2(ad[i], b0, acc2[i][0]);
                acc2[i][1] = ffma2(ad[i], b1, acc2[i][1]);
                acc2[i][2] = ffma2(ad[i], b2, acc2[i][2]);
                acc2[i][3] = ffma2(ad[i], b3, acc2[i][3]);
            }
        }
        __syncthreads();
    }

#pragma unroll
    for (int i = 0; i < 8; i++) {
        int grow = row0 + ty * 8 + i;
        if (grow < n) {
            float* dst = &g_xw[(size_t)grow * D];
            *(ull*)&dst[tx * 4]          = acc2[i][0];
            *(ull*)&dst[tx * 4 + 2]      = acc2[i][1];
            *(ull*)&dst[64 + tx * 4]     = acc2[i][2];
            *(ull*)&dst[64 + tx * 4 + 2] = acc2[i][3];
        }
    }
}

// ---------- pull aggregation: one warp per dst row, no feature atomics ----
__global__ __launch_bounds__(256)
void k_aggregate(const float* __restrict__ b, int n) {
    __shared__ float bs1[D];
    __shared__ float bs2[D];
    const int lane = threadIdx.x & 31;
    const int warp = threadIdx.x >> 5;
    const int warpGlobal = blockIdx.x * 8 + warp;
    const int totalWarps = gridDim.x * 8;

    if (threadIdx.x < D) { bs1[threadIdx.x] = 0.0f; bs2[threadIdx.x] = 0.0f; }
    __syncthreads();

    float4 bb = ((const float4*)b)[lane];
    float s1x = 0.f, s1y = 0.f, s1z = 0.f, s1w = 0.f;
    float s2x = 0.f, s2y = 0.f, s2z = 0.f, s2w = 0.f;

    for (int row = warpGlobal; row < n; row += totalWarps) {
        float dd = g_dinv[row];
        float selfc = dd * dd;
        float4 acc = bb;
        float4 xv = ((const float4*)g_xw)[(size_t)row * 32 + lane];
        acc.x = fmaf(xv.x, selfc, acc.x);
        acc.y = fmaf(xv.y, selfc, acc.y);
        acc.z = fmaf(xv.z, selfc, acc.z);
        acc.w = fmaf(xv.w, selfc, acc.w);

        int rs = g_rowstart[row];
        int deg = g_degi[row];
        for (int base = 0; base < deg; base += 32) {
            int e = base + lane;
            int s = 0; float cl = 0.0f;
            if (e < deg) {
                s = g_csr_src[rs + e];
                cl = g_dinv[s];
            }
            int cnt = min(32, deg - base);
            for (int j = 0; j < cnt; j++) {
                int sj = __shfl_sync(0xffffffff, s, j);
                float cj = __shfl_sync(0xffffffff, cl, j) * dd;
                float4 v = ((const float4*)g_xw)[(size_t)sj * 32 + lane];
                acc.x = fmaf(v.x, cj, acc.x);
                acc.y = fmaf(v.y, cj, acc.y);
                acc.z = fmaf(v.z, cj, acc.z);
                acc.w = fmaf(v.w, cj, acc.w);
            }
        }
        ((float4*)g_acc)[(size_t)row * 32 + lane] = acc;

        s1x += acc.x; s1y += acc.y; s1z += acc.z; s1w += acc.w;
        s2x = fmaf(acc.x, acc.x, s2x);
        s2y = fmaf(acc.y, acc.y, s2y);
        s2z = fmaf(acc.z, acc.z, s2z);
        s2w = fmaf(acc.w, acc.w, s2w);
    }

    atomicAdd(&bs1[lane * 4 + 0], s1x);
    atomicAdd(&bs1[lane * 4 + 1], s1y);
    atomicAdd(&bs1[lane * 4 + 2], s1z);
    atomicAdd(&bs1[lane * 4 + 3], s1w);
    atomicAdd(&bs2[lane * 4 + 0], s2x);
    atomicAdd(&bs2[lane * 4 + 1], s2y);
    atomicAdd(&bs2[lane * 4 + 2], s2z);
    atomicAdd(&bs2[lane * 4 + 3], s2w);
    __syncthreads();
    if (threadIdx.x < D) {
        atomicAdd(&g_sum[threadIdx.x], bs1[threadIdx.x]);
        atomicAdd(&g_sumsq[threadIdx.x], bs2[threadIdx.x]);
    }
}

__global__ void k_bnparams(const float* __restrict__ gamma,
                           const float* __restrict__ beta, int n) {
    int d = threadIdx.x;
    float inv_n = 1.0f / (float)n;
    float mean = g_sum[d] * inv_n;
    float var = g_sumsq[d] * inv_n - mean * mean;
    float sc = gamma[d] * rsqrtf(var + BN_EPS);
    g_scale[d] = sc;
    g_shift[d] = fmaf(-mean, sc, beta[d]);
}

// ---------- finalize: BN affine + PReLU + residual ----------
__global__ void k_final(const float* __restrict__ x,
                        const float* __restrict__ a_prelu,
                        float* __restrict__ out, int n) {
    int t = blockIdx.x * blockDim.x + threadIdx.x;
    if (t >= n * 32) return;
    int q = t & 31;
    float a = *a_prelu;
    float4 v  = ((const float4*)g_acc)[t];
    float4 sc = ((const float4*)g_scale)[q];
    float4 sh = ((const float4*)g_shift)[q];
    float4 xx = ((const float4*)x)[t];
    float4 r;
    r.x = fmaf(v.x, sc.x, sh.x); r.x = (r.x > 0.f ? r.x : a * r.x) + xx.x;
    r.y = fmaf(v.y, sc.y, sh.y); r.y = (r.y > 0.f ? r.y : a * r.y) + xx.y;
    r.z = fmaf(v.z, sc.z, sh.z); r.z = (r.z > 0.f ? r.z : a * r.z) + xx.z;
    r.w = fmaf(v.w, sc.w, sh.w); r.w = (r.w > 0.f ? r.w : a * r.w) + xx.w;
    ((float4*)out)[t] = r;
}

extern "C" void kernel_launch(void* const* d_in, const int* in_sizes, int n_in,
                              void* d_out, int out_size) {
    const float* x       = (const float*)d_in[0];
    const float* W       = (const float*)d_in[1];
    const float* b       = (const float*)d_in[2];
    const float* gamma   = (const float*)d_in[3];
    const float* beta    = (const float*)d_in[4];
    const float* a_prelu = (const float*)d_in[5];
    const int*   ei      = (const int*)d_in[6];

    int n = in_sizes[0] / D;
    int E = in_sizes[6] / 2;
    const int* src = ei;
    const int* dst = ei + E;
    float* out = (float*)d_out;

    int scanBlocks = (n + SCAN_EPB - 1) / SCAN_EPB;

    k_init<<<(n + 255) / 256, 256>>>(n);
    k_deg<<<(E + 255) / 256, 256>>>(dst, E);
    k_scan1<<<scanBlocks, SCAN_TPB>>>(n);
    k_scan2<<<1, 256>>>(scanBlocks);
    k_scan3<<<(n + 255) / 256, 256>>>(n);
    k_fill<<<(E + 255) / 256, 256>>>(src, dst, E);
    k_gemm<<<(n + 127) / 128, 256>>>(x, W, n);
    k_aggregate<<<2048, 256>>>(b, n);
    k_bnparams<<<1, 128>>>(gamma, beta, n);
    k_final<<<(n * 32 + 255) / 256, 256>>>(x, a_prelu, out, n);
}